// round 7
// baseline (speedup 1.0000x reference)
#include <cuda_runtime.h>
#include <cuda_fp16.h>
#include <cstdint>

// ---------------------------------------------------------------------------
// GCN_40037685134216: 4-layer GCN + mean-pool + MLP head, fp32.
// R7: scatter inner loop -> explicit 8-deep load pipeline (MLP 4 -> 8),
//     dual accumulators. fp16 y + 3xTF32 GEMM as R6.
// ---------------------------------------------------------------------------

#define MAX_N 100000
#define MAX_E 1600000
#define DD    128
#define MAX_G 512
#define SCAN_BLK 1024
#define NB ((MAX_N + SCAN_BLK - 1) / SCAN_BLK)   // 98

__device__ __align__(16) int    g_cnt [MAX_N];
__device__ __align__(16) int    g_rowptr[MAX_N + 1];
__device__ __align__(16) int    g_cur [MAX_N];
__device__ __align__(16) int    g_eadj[MAX_E];
__device__ __align__(16) float  g_dinv[MAX_N];
__device__ __align__(16) int    g_bsum[NB];
__device__ __align__(16) int    g_boff[NB];
__device__ __align__(16) __half2 g_y [MAX_N * (DD/2)];   // fp16 messages
__device__ float4 g_hA [MAX_N * (DD/4)];
__device__ float4 g_hB [MAX_N * (DD/4)];
__device__ float4 g_psum[MAX_G * (DD/4)];
__device__ float  g_pcnt[MAX_G];

// ---------------------------------------------------------------------------
// CSR build
// ---------------------------------------------------------------------------
__global__ void k_zero_cnt(int* cnt, int N) {
    int i = blockIdx.x * blockDim.x + threadIdx.x;
    if (i < N) cnt[i] = 0;
}

__global__ void k_count(const int* __restrict__ ei, int* cnt, int E) {
    int e = blockIdx.x * blockDim.x + threadIdx.x;
    if (e < E) atomicAdd(&cnt[ei[E + e]], 1);
}

__global__ void k_dinv(const int* __restrict__ cnt, float* dinv, int N) {
    int i = blockIdx.x * blockDim.x + threadIdx.x;
    if (i < N) dinv[i] = rsqrtf((float)cnt[i] + 1.0f);  // +1 self loop
}

__global__ __launch_bounds__(256)
void k_blocksum(const int* __restrict__ cnt, int* __restrict__ bsum, int N) {
    __shared__ int red[8];
    int b = blockIdx.x, t = threadIdx.x;
    int base = b * SCAN_BLK;
    int s = 0;
#pragma unroll
    for (int j = 0; j < 4; j++) {
        int i = base + t + j * 256;
        if (i < N) s += cnt[i];
    }
#pragma unroll
    for (int off = 16; off > 0; off >>= 1)
        s += __shfl_down_sync(0xffffffffu, s, off);
    if ((t & 31) == 0) red[t >> 5] = s;
    __syncthreads();
    if (t < 8) {
        s = red[t];
#pragma unroll
        for (int off = 4; off > 0; off >>= 1)
            s += __shfl_down_sync(0xffu, s, off);
        if (t == 0) bsum[b] = s;
    }
}

__global__ __launch_bounds__(128)
void k_scanbsum(const int* __restrict__ bsum, int* __restrict__ boff,
                int* __restrict__ rowptr, int nb, int N, int E) {
    __shared__ int s[128];
    int t = threadIdx.x;
    int v = (t < nb) ? bsum[t] : 0;
    s[t] = v;
    __syncthreads();
    for (int off = 1; off < 128; off <<= 1) {
        int u = (t >= off) ? s[t - off] : 0;
        __syncthreads();
        s[t] += u;
        __syncthreads();
    }
    if (t < nb) boff[t] = s[t] - v;
    if (t == 0) rowptr[N] = E;
}

__global__ __launch_bounds__(SCAN_BLK)
void k_scanblock(const int* __restrict__ cnt, const int* __restrict__ boff,
                 int* __restrict__ rowptr, int* __restrict__ cur, int N) {
    __shared__ int s[SCAN_BLK];
    int b = blockIdx.x, t = threadIdx.x;
    int i = b * SCAN_BLK + t;
    int v = (i < N) ? cnt[i] : 0;
    s[t] = v;
    __syncthreads();
    for (int off = 1; off < SCAN_BLK; off <<= 1) {
        int u = (t >= off) ? s[t - off] : 0;
        __syncthreads();
        s[t] += u;
        __syncthreads();
    }
    if (i < N) {
        int ex = boff[b] + s[t] - v;
        rowptr[i] = ex;
        cur[i]    = ex;
    }
}

__global__ void k_fill(const int* __restrict__ ei, int* cur,
                       int* __restrict__ eadj, int E) {
    int e = blockIdx.x * blockDim.x + threadIdx.x;
    if (e < E) {
        int r = ei[e];
        int c = ei[E + e];
        int pos = atomicAdd(&cur[c], 1);
        eadj[pos] = r;
    }
}

// ---------------------------------------------------------------------------
// TF32 tensor-core GEMM: Y[M,128] = fp16( dinv[m] * ( act(A[M,128]) @ W ) )
// ---------------------------------------------------------------------------
#define BM 128
#define PA 20
#define PW 136

__device__ __forceinline__ uint32_t f2tf32(float x) {
    uint32_t r;
    asm("cvt.rna.tf32.f32 %0, %1;" : "=r"(r) : "f"(x));
    return r;
}

__device__ __forceinline__ void split_tf32(float x, uint32_t& hi, uint32_t& lo) {
    hi = f2tf32(x);
    lo = f2tf32(x - __uint_as_float(hi));
}

__device__ __forceinline__ void mma_tf32(float* c, const uint32_t* a, const uint32_t* b) {
    asm volatile("mma.sync.aligned.m16n8k8.row.col.f32.tf32.tf32.f32 "
                 "{%0,%1,%2,%3}, {%4,%5,%6,%7}, {%8,%9}, {%0,%1,%2,%3};"
                 : "+f"(c[0]), "+f"(c[1]), "+f"(c[2]), "+f"(c[3])
                 : "r"(a[0]), "r"(a[1]), "r"(a[2]), "r"(a[3]),
                   "r"(b[0]), "r"(b[1]));
}

__global__ __launch_bounds__(256)
void k_gemm_tf32(const float4* __restrict__ A4, const float4* __restrict__ W4,
                 __half2* __restrict__ Y2, const float* __restrict__ dinv,
                 int M, int applyRelu) {
    __shared__ uint32_t Ah[BM * PA], Al[BM * PA];
    __shared__ uint32_t Wh[16 * PW], Wl[16 * PW];

    const int tid  = threadIdx.x;
    const int lane = tid & 31;
    const int wid  = tid >> 5;
    const int wm   = wid & 3;
    const int wn   = wid >> 2;
    const int grp  = lane >> 2;
    const int tig  = lane & 3;
    const int m0   = blockIdx.x * BM;

    float acc[2][8][4];
#pragma unroll
    for (int f = 0; f < 2; f++)
#pragma unroll
        for (int g = 0; g < 8; g++)
#pragma unroll
            for (int j = 0; j < 4; j++) acc[f][g][j] = 0.0f;

    for (int k0 = 0; k0 < DD; k0 += 16) {
#pragma unroll
        for (int i = 0; i < 2; i++) {
            int id  = tid + i * 256;
            int row = id >> 2;
            int q   = id & 3;
            float4 v = make_float4(0.f, 0.f, 0.f, 0.f);
            int gr = m0 + row;
            if (gr < M) v = A4[gr * (DD/4) + (k0 >> 2) + q];
            if (applyRelu) {
                v.x = fmaxf(v.x, 0.f); v.y = fmaxf(v.y, 0.f);
                v.z = fmaxf(v.z, 0.f); v.w = fmaxf(v.w, 0.f);
            }
            uint32_t h0, l0, h1, l1, h2, l2, h3, l3;
            split_tf32(v.x, h0, l0); split_tf32(v.y, h1, l1);
            split_tf32(v.z, h2, l2); split_tf32(v.w, h3, l3);
            int base = row * PA + q * 4;
            Ah[base + 0] = h0; Ah[base + 1] = h1; Ah[base + 2] = h2; Ah[base + 3] = h3;
            Al[base + 0] = l0; Al[base + 1] = l1; Al[base + 2] = l2; Al[base + 3] = l3;
        }
#pragma unroll
        for (int i = 0; i < 2; i++) {
            int id = tid + i * 256;
            int kk = id >> 5;
            int nq = id & 31;
            float4 v = W4[(k0 + kk) * (DD/4) + nq];
            uint32_t h0, l0, h1, l1, h2, l2, h3, l3;
            split_tf32(v.x, h0, l0); split_tf32(v.y, h1, l1);
            split_tf32(v.z, h2, l2); split_tf32(v.w, h3, l3);
            int base = kk * PW + nq * 4;
            Wh[base + 0] = h0; Wh[base + 1] = h1; Wh[base + 2] = h2; Wh[base + 3] = h3;
            Wl[base + 0] = l0; Wl[base + 1] = l1; Wl[base + 2] = l2; Wl[base + 3] = l3;
        }
        __syncthreads();

#pragma unroll
        for (int kk = 0; kk < 16; kk += 8) {
            uint32_t ah[2][4], al[2][4];
#pragma unroll
            for (int f = 0; f < 2; f++) {
                int r0 = wm * 32 + f * 16 + grp;
                ah[f][0] = Ah[r0 * PA + kk + tig];
                ah[f][1] = Ah[(r0 + 8) * PA + kk + tig];
                ah[f][2] = Ah[r0 * PA + kk + tig + 4];
                ah[f][3] = Ah[(r0 + 8) * PA + kk + tig + 4];
                al[f][0] = Al[r0 * PA + kk + tig];
                al[f][1] = Al[(r0 + 8) * PA + kk + tig];
                al[f][2] = Al[r0 * PA + kk + tig + 4];
                al[f][3] = Al[(r0 + 8) * PA + kk + tig + 4];
            }
            uint32_t bh[8][2], bl[8][2];
#pragma unroll
            for (int g = 0; g < 8; g++) {
                int n = wn * 64 + g * 8 + grp;
                bh[g][0] = Wh[(kk + tig) * PW + n];
                bh[g][1] = Wh[(kk + tig + 4) * PW + n];
                bl[g][0] = Wl[(kk + tig) * PW + n];
                bl[g][1] = Wl[(kk + tig + 4) * PW + n];
            }
#pragma unroll
            for (int f = 0; f < 2; f++)
#pragma unroll
                for (int g = 0; g < 8; g++) {
                    mma_tf32(acc[f][g], ah[f], bl[g]);
                    mma_tf32(acc[f][g], al[f], bh[g]);
                    mma_tf32(acc[f][g], ah[f], bh[g]);
                }
        }
        __syncthreads();
    }

#pragma unroll
    for (int f = 0; f < 2; f++) {
        int r0 = m0 + wm * 32 + f * 16 + grp;
        int r1 = r0 + 8;
        float d0 = (r0 < M) ? dinv[r0] : 0.f;
        float d1 = (r1 < M) ? dinv[r1] : 0.f;
#pragma unroll
        for (int g = 0; g < 8; g++) {
            int c = wn * 64 + g * 8 + tig * 2;
            if (r0 < M)
                Y2[(size_t)r0 * (DD/2) + (c >> 1)] =
                    __floats2half2_rn(acc[f][g][0] * d0, acc[f][g][1] * d0);
            if (r1 < M)
                Y2[(size_t)r1 * (DD/2) + (c >> 1)] =
                    __floats2half2_rn(acc[f][g][2] * d1, acc[f][g][3] * d1);
        }
    }
}

// ---------------------------------------------------------------------------
// CSR scatter: one warp per node; 8-deep explicit load pipeline.
// ---------------------------------------------------------------------------
__device__ __forceinline__ void red_add_v4(float* addr, float4 v) {
    asm volatile("red.global.add.v4.f32 [%0], {%1, %2, %3, %4};"
                 :: "l"(addr), "f"(v.x), "f"(v.y), "f"(v.z), "f"(v.w)
                 : "memory");
}

__device__ __forceinline__ void acc_half4(float4& acc, uint2 raw) {
    __half2 h01 = *reinterpret_cast<__half2*>(&raw.x);
    __half2 h23 = *reinterpret_cast<__half2*>(&raw.y);
    float2 f01 = __half22float2(h01);
    float2 f23 = __half22float2(h23);
    acc.x += f01.x; acc.y += f01.y; acc.z += f23.x; acc.w += f23.y;
}

__global__ __launch_bounds__(256)
void k_scatter_csr(const uint2* __restrict__ y2,   // [N][32] uint2 (=4 halves)
                   const int* __restrict__ rowptr,
                   const int* __restrict__ eadj,
                   const float* __restrict__ dinv,
                   const float* __restrict__ bias,
                   float4* __restrict__ out4,
                   const int* __restrict__ batch,   // non-null => pool mode
                   float4* __restrict__ psum, float* __restrict__ pcnt,
                   int N) {
    int node = (blockIdx.x * blockDim.x + threadIdx.x) >> 5;
    int lane = threadIdx.x & 31;
    if (node >= N) return;

    int beg = rowptr[node];
    int end = rowptr[node + 1];
    int deg = end - beg;

    float4 acc0 = make_float4(0.f, 0.f, 0.f, 0.f);
    float4 acc1 = make_float4(0.f, 0.f, 0.f, 0.f);
    acc_half4(acc0, __ldg(&y2[(size_t)node * 32 + lane]));   // self loop

    for (int base = 0; base < deg; base += 32) {
        int n = min(32, deg - base);
        int s = (base + lane < deg) ? eadj[beg + base + lane] : 0;

        int j = 0;
        // 8-deep pipelined body: 8 independent loads in flight per warp
        for (; j + 8 <= n; j += 8) {
            uint2 v0, v1, v2, v3, v4, v5, v6, v7;
            {
                int s0 = __shfl_sync(0xffffffffu, s, j + 0);
                int s1 = __shfl_sync(0xffffffffu, s, j + 1);
                int s2 = __shfl_sync(0xffffffffu, s, j + 2);
                int s3 = __shfl_sync(0xffffffffu, s, j + 3);
                int s4 = __shfl_sync(0xffffffffu, s, j + 4);
                int s5 = __shfl_sync(0xffffffffu, s, j + 5);
                int s6 = __shfl_sync(0xffffffffu, s, j + 6);
                int s7 = __shfl_sync(0xffffffffu, s, j + 7);
                v0 = __ldg(&y2[(size_t)s0 * 32 + lane]);
                v1 = __ldg(&y2[(size_t)s1 * 32 + lane]);
                v2 = __ldg(&y2[(size_t)s2 * 32 + lane]);
                v3 = __ldg(&y2[(size_t)s3 * 32 + lane]);
                v4 = __ldg(&y2[(size_t)s4 * 32 + lane]);
                v5 = __ldg(&y2[(size_t)s5 * 32 + lane]);
                v6 = __ldg(&y2[(size_t)s6 * 32 + lane]);
                v7 = __ldg(&y2[(size_t)s7 * 32 + lane]);
            }
            acc_half4(acc0, v0); acc_half4(acc1, v1);
            acc_half4(acc0, v2); acc_half4(acc1, v3);
            acc_half4(acc0, v4); acc_half4(acc1, v5);
            acc_half4(acc0, v6); acc_half4(acc1, v7);
        }
        // tail
        for (; j < n; j++) {
            int src = __shfl_sync(0xffffffffu, s, j);
            acc_half4(acc0, __ldg(&y2[(size_t)src * 32 + lane]));
        }
    }

    float4 acc = make_float4(acc0.x + acc1.x, acc0.y + acc1.y,
                             acc0.z + acc1.z, acc0.w + acc1.w);
    float di = dinv[node];
    const float4 b = ((const float4*)bias)[lane];
    float4 o;
    o.x = fmaf(acc.x, di, b.x);
    o.y = fmaf(acc.y, di, b.y);
    o.z = fmaf(acc.z, di, b.z);
    o.w = fmaf(acc.w, di, b.w);

    if (batch) {
        int g = batch[node];
        red_add_v4((float*)(psum + g * (DD/4) + lane), o);
        if (lane == 0) atomicAdd(&pcnt[g], 1.0f);
    } else {
        out4[(size_t)node * (DD/4) + lane] = o;
    }
}

// ---------------------------------------------------------------------------
// Pool zero + MLP head
// ---------------------------------------------------------------------------
__global__ void k_zero_pool(float4* psum, float* pcnt, int G) {
    int t = blockIdx.x * blockDim.x + threadIdx.x;
    if (t < G * (DD/4)) psum[t] = make_float4(0.f, 0.f, 0.f, 0.f);
    if (t < G) pcnt[t] = 0.f;
}

__global__ __launch_bounds__(128)
void k_mlp(const float4* __restrict__ psum, const float* __restrict__ pcnt,
           const float* __restrict__ w1, const float* __restrict__ b1,
           const float* __restrict__ w2, const float* __restrict__ b2,
           float* __restrict__ out, int H) {
    __shared__ float p[DD];
    __shared__ float hid[128];
    int g   = blockIdx.x;
    int tid = threadIdx.x;

    float cnt = fmaxf(pcnt[g], 1.0f);
    float inv = 1.0f / cnt;
    const float* ps = (const float*)(psum + g * (DD/4));
    p[tid] = ps[tid] * inv;
    __syncthreads();

    if (tid < H) {
        float s = b1[tid];
#pragma unroll 8
        for (int k = 0; k < DD; k++) s += p[k] * w1[k * H + tid];
        hid[tid] = fmaxf(s, 0.f);
    }
    __syncthreads();

    if (tid < 4) {
        float s = b2[tid];
        for (int j = 0; j < H; j++) s += hid[j] * w2[j * 4 + tid];
        out[g * 4 + tid] = s;
    }
}

// ---------------------------------------------------------------------------
// Launch
// ---------------------------------------------------------------------------
extern "C" void kernel_launch(void* const* d_in, const int* in_sizes, int n_in,
                              void* d_out, int out_size) {
    const float* x     = (const float*)d_in[0];
    const float* Ws    = (const float*)d_in[1];
    const float* bs    = (const float*)d_in[2];
    const float* w1    = (const float*)d_in[3];
    const float* b1    = (const float*)d_in[4];
    const float* w2    = (const float*)d_in[5];
    const float* b2    = (const float*)d_in[6];
    const int*   ei    = (const int*)d_in[7];
    const int*   batch = (const int*)d_in[8];
    float*       out   = (float*)d_out;

    const int N = in_sizes[8];          // 100000
    const int E = in_sizes[7] / 2;      // 1600000
    const int G = out_size / 4;         // 512
    const int H = in_sizes[4];          // 100

    int *cnt, *rowptr, *cur, *eadj, *bsum, *boff;
    float *dinv, *pcnt;
    __half2* y;
    float4 *hA, *hB, *psum;
    cudaGetSymbolAddress((void**)&cnt,    g_cnt);
    cudaGetSymbolAddress((void**)&rowptr, g_rowptr);
    cudaGetSymbolAddress((void**)&cur,    g_cur);
    cudaGetSymbolAddress((void**)&eadj,   g_eadj);
    cudaGetSymbolAddress((void**)&bsum,   g_bsum);
    cudaGetSymbolAddress((void**)&boff,   g_boff);
    cudaGetSymbolAddress((void**)&dinv,   g_dinv);
    cudaGetSymbolAddress((void**)&y,      g_y);
    cudaGetSymbolAddress((void**)&hA,     g_hA);
    cudaGetSymbolAddress((void**)&hB,     g_hB);
    cudaGetSymbolAddress((void**)&psum,   g_psum);
    cudaGetSymbolAddress((void**)&pcnt,   g_pcnt);

    const int T  = 256;
    const int nb = (N + SCAN_BLK - 1) / SCAN_BLK;

    // CSR build + normalization
    k_zero_cnt <<<(N + T - 1) / T, T>>>(cnt, N);
    k_count    <<<(E + T - 1) / T, T>>>(ei, cnt, E);
    k_dinv     <<<(N + T - 1) / T, T>>>(cnt, dinv, N);
    k_blocksum <<<nb, 256>>>(cnt, bsum, N);
    k_scanbsum <<<1, 128>>>(bsum, boff, rowptr, nb, N, E);
    k_scanblock<<<nb, SCAN_BLK>>>(cnt, boff, rowptr, cur, N);
    k_fill     <<<(E + T - 1) / T, T>>>(ei, cur, eadj, E);
    k_zero_pool<<<(G * (DD/4) + T - 1) / T, T>>>(psum, pcnt, G);

    // 4 GCN layers
    const float4* hin = (const float4*)x;
    const int gemmBlocks = (N + BM - 1) / BM;
    const int nodeWarpBlocks = (N + 7) / 8;
    for (int L = 0; L < 4; L++) {
        const float4* W4 = (const float4*)(Ws + (size_t)L * DD * DD);
        k_gemm_tf32<<<gemmBlocks, 256>>>(hin, W4, y, dinv, N, L > 0 ? 1 : 0);
        float4* hout = (L & 1) ? hB : hA;
        if (L < 3) {
            k_scatter_csr<<<nodeWarpBlocks, 256>>>((const uint2*)y, rowptr, eadj, dinv,
                                                   bs + L * DD, hout,
                                                   nullptr, nullptr, nullptr, N);
            hin = hout;
        } else {
            k_scatter_csr<<<nodeWarpBlocks, 256>>>((const uint2*)y, rowptr, eadj, dinv,
                                                   bs + L * DD, nullptr,
                                                   batch, psum, pcnt, N);
        }
    }

    k_mlp<<<G, 128>>>(psum, pcnt, w1, b1, w2, b2, out, H);
}

// round 8
// speedup vs baseline: 1.0410x; 1.0410x over previous
#include <cuda_runtime.h>
#include <cuda_fp16.h>
#include <cstdint>

// ---------------------------------------------------------------------------
// GCN_40037685134216: 4-layer GCN + mean-pool + MLP head, fp32.
// R8: revert scatter to R6 form; reorder launches so GEMM is the 4th launch
//     (ncu capture slot); pre-split W into tf32 hi/lo planes once per call.
// ---------------------------------------------------------------------------

#define MAX_N 100000
#define MAX_E 1600000
#define DD    128
#define MAX_G 512
#define SCAN_BLK 1024
#define NB ((MAX_N + SCAN_BLK - 1) / SCAN_BLK)   // 98
#define WTOT (4 * DD * DD)                        // 65536

__device__ __align__(16) int    g_cnt [MAX_N];
__device__ __align__(16) int    g_rowptr[MAX_N + 1];
__device__ __align__(16) int    g_cur [MAX_N];
__device__ __align__(16) int    g_eadj[MAX_E];
__device__ __align__(16) float  g_dinv[MAX_N];
__device__ __align__(16) int    g_bsum[NB];
__device__ __align__(16) int    g_boff[NB];
__device__ __align__(16) uint32_t g_Whi[WTOT];
__device__ __align__(16) uint32_t g_Wlo[WTOT];
__device__ __align__(16) __half2 g_y [MAX_N * (DD/2)];   // fp16 messages
__device__ float4 g_hA [MAX_N * (DD/4)];
__device__ float4 g_hB [MAX_N * (DD/4)];
__device__ float4 g_psum[MAX_G * (DD/4)];
__device__ float  g_pcnt[MAX_G];

__device__ __forceinline__ uint32_t f2tf32(float x) {
    uint32_t r;
    asm("cvt.rna.tf32.f32 %0, %1;" : "=r"(r) : "f"(x));
    return r;
}

__device__ __forceinline__ void split_tf32(float x, uint32_t& hi, uint32_t& lo) {
    hi = f2tf32(x);
    lo = f2tf32(x - __uint_as_float(hi));
}

// ---------------------------------------------------------------------------
// zero cnt + pre-split all 4 W matrices into tf32 hi/lo
// ---------------------------------------------------------------------------
__global__ void k_zero_cnt_splitW(int* cnt, int N, const float* __restrict__ Ws,
                                  uint32_t* __restrict__ Whi, uint32_t* __restrict__ Wlo) {
    int i = blockIdx.x * blockDim.x + threadIdx.x;
    if (i < N) cnt[i] = 0;
    if (i < WTOT) {
        uint32_t h, l;
        split_tf32(Ws[i], h, l);
        Whi[i] = h;
        Wlo[i] = l;
    }
}

__global__ void k_count(const int* __restrict__ ei, int* cnt, int E) {
    int e = blockIdx.x * blockDim.x + threadIdx.x;
    if (e < E) atomicAdd(&cnt[ei[E + e]], 1);
}

__global__ void k_dinv(const int* __restrict__ cnt, float* dinv, int N) {
    int i = blockIdx.x * blockDim.x + threadIdx.x;
    if (i < N) dinv[i] = rsqrtf((float)cnt[i] + 1.0f);  // +1 self loop
}

__global__ __launch_bounds__(256)
void k_blocksum(const int* __restrict__ cnt, int* __restrict__ bsum, int N) {
    __shared__ int red[8];
    int b = blockIdx.x, t = threadIdx.x;
    int base = b * SCAN_BLK;
    int s = 0;
#pragma unroll
    for (int j = 0; j < 4; j++) {
        int i = base + t + j * 256;
        if (i < N) s += cnt[i];
    }
#pragma unroll
    for (int off = 16; off > 0; off >>= 1)
        s += __shfl_down_sync(0xffffffffu, s, off);
    if ((t & 31) == 0) red[t >> 5] = s;
    __syncthreads();
    if (t < 8) {
        s = red[t];
#pragma unroll
        for (int off = 4; off > 0; off >>= 1)
            s += __shfl_down_sync(0xffu, s, off);
        if (t == 0) bsum[b] = s;
    }
}

__global__ __launch_bounds__(128)
void k_scanbsum(const int* __restrict__ bsum, int* __restrict__ boff,
                int* __restrict__ rowptr, int nb, int N, int E) {
    __shared__ int s[128];
    int t = threadIdx.x;
    int v = (t < nb) ? bsum[t] : 0;
    s[t] = v;
    __syncthreads();
    for (int off = 1; off < 128; off <<= 1) {
        int u = (t >= off) ? s[t - off] : 0;
        __syncthreads();
        s[t] += u;
        __syncthreads();
    }
    if (t < nb) boff[t] = s[t] - v;
    if (t == 0) rowptr[N] = E;
}

__global__ __launch_bounds__(SCAN_BLK)
void k_scanblock(const int* __restrict__ cnt, const int* __restrict__ boff,
                 int* __restrict__ rowptr, int* __restrict__ cur, int N) {
    __shared__ int s[SCAN_BLK];
    int b = blockIdx.x, t = threadIdx.x;
    int i = b * SCAN_BLK + t;
    int v = (i < N) ? cnt[i] : 0;
    s[t] = v;
    __syncthreads();
    for (int off = 1; off < SCAN_BLK; off <<= 1) {
        int u = (t >= off) ? s[t - off] : 0;
        __syncthreads();
        s[t] += u;
        __syncthreads();
    }
    if (i < N) {
        int ex = boff[b] + s[t] - v;
        rowptr[i] = ex;
        cur[i]    = ex;
    }
}

__global__ void k_fill(const int* __restrict__ ei, int* cur,
                       int* __restrict__ eadj, int E) {
    int e = blockIdx.x * blockDim.x + threadIdx.x;
    if (e < E) {
        int r = ei[e];
        int c = ei[E + e];
        int pos = atomicAdd(&cur[c], 1);
        eadj[pos] = r;
    }
}

// ---------------------------------------------------------------------------
// TF32 tensor-core GEMM: Y[M,128] = fp16( dinv[m] * ( act(A[M,128]) @ W ) )
// W pre-split into tf32 hi/lo planes in global memory.
// ---------------------------------------------------------------------------
#define BM 128
#define PA 20
#define PW 136

__device__ __forceinline__ void mma_tf32(float* c, const uint32_t* a, const uint32_t* b) {
    asm volatile("mma.sync.aligned.m16n8k8.row.col.f32.tf32.tf32.f32 "
                 "{%0,%1,%2,%3}, {%4,%5,%6,%7}, {%8,%9}, {%0,%1,%2,%3};"
                 : "+f"(c[0]), "+f"(c[1]), "+f"(c[2]), "+f"(c[3])
                 : "r"(a[0]), "r"(a[1]), "r"(a[2]), "r"(a[3]),
                   "r"(b[0]), "r"(b[1]));
}

__global__ __launch_bounds__(256)
void k_gemm_tf32(const float4* __restrict__ A4,
                 const uint4* __restrict__ Whi4, const uint4* __restrict__ Wlo4,
                 __half2* __restrict__ Y2, const float* __restrict__ dinv,
                 int M, int applyRelu) {
    __shared__ uint32_t Ah[BM * PA], Al[BM * PA];
    __shared__ uint32_t Wh[16 * PW], Wl[16 * PW];

    const int tid  = threadIdx.x;
    const int lane = tid & 31;
    const int wid  = tid >> 5;
    const int wm   = wid & 3;
    const int wn   = wid >> 2;
    const int grp  = lane >> 2;
    const int tig  = lane & 3;
    const int m0   = blockIdx.x * BM;

    float acc[2][8][4];
#pragma unroll
    for (int f = 0; f < 2; f++)
#pragma unroll
        for (int g = 0; g < 8; g++)
#pragma unroll
            for (int j = 0; j < 4; j++) acc[f][g][j] = 0.0f;

    for (int k0 = 0; k0 < DD; k0 += 16) {
#pragma unroll
        for (int i = 0; i < 2; i++) {
            int id  = tid + i * 256;
            int row = id >> 2;
            int q   = id & 3;
            float4 v = make_float4(0.f, 0.f, 0.f, 0.f);
            int gr = m0 + row;
            if (gr < M) v = A4[gr * (DD/4) + (k0 >> 2) + q];
            if (applyRelu) {
                v.x = fmaxf(v.x, 0.f); v.y = fmaxf(v.y, 0.f);
                v.z = fmaxf(v.z, 0.f); v.w = fmaxf(v.w, 0.f);
            }
            uint32_t h0, l0, h1, l1, h2, l2, h3, l3;
            split_tf32(v.x, h0, l0); split_tf32(v.y, h1, l1);
            split_tf32(v.z, h2, l2); split_tf32(v.w, h3, l3);
            int base = row * PA + q * 4;
            Ah[base + 0] = h0; Ah[base + 1] = h1; Ah[base + 2] = h2; Ah[base + 3] = h3;
            Al[base + 0] = l0; Al[base + 1] = l1; Al[base + 2] = l2; Al[base + 3] = l3;
        }
#pragma unroll
        for (int i = 0; i < 2; i++) {
            int id = tid + i * 256;
            int kk = id >> 5;
            int nq = id & 31;
            uint4 vh = Whi4[(k0 + kk) * (DD/4) + nq];
            uint4 vl = Wlo4[(k0 + kk) * (DD/4) + nq];
            int base = kk * PW + nq * 4;
            Wh[base + 0] = vh.x; Wh[base + 1] = vh.y; Wh[base + 2] = vh.z; Wh[base + 3] = vh.w;
            Wl[base + 0] = vl.x; Wl[base + 1] = vl.y; Wl[base + 2] = vl.z; Wl[base + 3] = vl.w;
        }
        __syncthreads();

#pragma unroll
        for (int kk = 0; kk < 16; kk += 8) {
            uint32_t ah[2][4], al[2][4];
#pragma unroll
            for (int f = 0; f < 2; f++) {
                int r0 = wm * 32 + f * 16 + grp;
                ah[f][0] = Ah[r0 * PA + kk + tig];
                ah[f][1] = Ah[(r0 + 8) * PA + kk + tig];
                ah[f][2] = Ah[r0 * PA + kk + tig + 4];
                ah[f][3] = Ah[(r0 + 8) * PA + kk + tig + 4];
                al[f][0] = Al[r0 * PA + kk + tig];
                al[f][1] = Al[(r0 + 8) * PA + kk + tig];
                al[f][2] = Al[r0 * PA + kk + tig + 4];
                al[f][3] = Al[(r0 + 8) * PA + kk + tig + 4];
            }
            uint32_t bh[8][2], bl[8][2];
#pragma unroll
            for (int g = 0; g < 8; g++) {
                int n = wn * 64 + g * 8 + grp;
                bh[g][0] = Wh[(kk + tig) * PW + n];
                bh[g][1] = Wh[(kk + tig + 4) * PW + n];
                bl[g][0] = Wl[(kk + tig) * PW + n];
                bl[g][1] = Wl[(kk + tig + 4) * PW + n];
            }
#pragma unroll
            for (int f = 0; f < 2; f++)
#pragma unroll
                for (int g = 0; g < 8; g++) {
                    mma_tf32(acc[f][g], ah[f], bl[g]);
                    mma_tf32(acc[f][g], al[f], bh[g]);
                    mma_tf32(acc[f][g], ah[f], bh[g]);
                }
        }
        __syncthreads();
    }

#pragma unroll
    for (int f = 0; f < 2; f++) {
        int r0 = m0 + wm * 32 + f * 16 + grp;
        int r1 = r0 + 8;
        float d0 = (r0 < M) ? dinv[r0] : 0.f;
        float d1 = (r1 < M) ? dinv[r1] : 0.f;
#pragma unroll
        for (int g = 0; g < 8; g++) {
            int c = wn * 64 + g * 8 + tig * 2;
            if (r0 < M)
                Y2[(size_t)r0 * (DD/2) + (c >> 1)] =
                    __floats2half2_rn(acc[f][g][0] * d0, acc[f][g][1] * d0);
            if (r1 < M)
                Y2[(size_t)r1 * (DD/2) + (c >> 1)] =
                    __floats2half2_rn(acc[f][g][2] * d1, acc[f][g][3] * d1);
        }
    }
}

// ---------------------------------------------------------------------------
// CSR scatter (R6 form): one warp per node.
// ---------------------------------------------------------------------------
__device__ __forceinline__ void red_add_v4(float* addr, float4 v) {
    asm volatile("red.global.add.v4.f32 [%0], {%1, %2, %3, %4};"
                 :: "l"(addr), "f"(v.x), "f"(v.y), "f"(v.z), "f"(v.w)
                 : "memory");
}

__device__ __forceinline__ void acc_half4(float4& acc, uint2 raw) {
    __half2 h01 = *reinterpret_cast<__half2*>(&raw.x);
    __half2 h23 = *reinterpret_cast<__half2*>(&raw.y);
    float2 f01 = __half22float2(h01);
    float2 f23 = __half22float2(h23);
    acc.x += f01.x; acc.y += f01.y; acc.z += f23.x; acc.w += f23.y;
}

__global__ __launch_bounds__(256)
void k_scatter_csr(const uint2* __restrict__ y2,   // [N][32] uint2 (=4 halves)
                   const int* __restrict__ rowptr,
                   const int* __restrict__ eadj,
                   const float* __restrict__ dinv,
                   const float* __restrict__ bias,
                   float4* __restrict__ out4,
                   const int* __restrict__ batch,   // non-null => pool mode
                   float4* __restrict__ psum, float* __restrict__ pcnt,
                   int N) {
    int node = (blockIdx.x * blockDim.x + threadIdx.x) >> 5;
    int lane = threadIdx.x & 31;
    if (node >= N) return;

    int beg = rowptr[node];
    int end = rowptr[node + 1];

    float4 acc = make_float4(0.f, 0.f, 0.f, 0.f);
    acc_half4(acc, y2[(size_t)node * 32 + lane]);   // self loop
    for (int base = beg; base < end; base += 32) {
        int n = min(32, end - base);
        int s = (base + lane < end) ? eadj[base + lane] : 0;
#pragma unroll 4
        for (int j = 0; j < n; j++) {
            int src = __shfl_sync(0xffffffffu, s, j);
            acc_half4(acc, y2[(size_t)src * 32 + lane]);
        }
    }
    float di = dinv[node];
    const float4 b = ((const float4*)bias)[lane];
    float4 o;
    o.x = fmaf(acc.x, di, b.x);
    o.y = fmaf(acc.y, di, b.y);
    o.z = fmaf(acc.z, di, b.z);
    o.w = fmaf(acc.w, di, b.w);

    if (batch) {
        int g = batch[node];
        red_add_v4((float*)(psum + g * (DD/4) + lane), o);
        if (lane == 0) atomicAdd(&pcnt[g], 1.0f);
    } else {
        out4[(size_t)node * (DD/4) + lane] = o;
    }
}

// ---------------------------------------------------------------------------
// Pool zero + MLP head
// ---------------------------------------------------------------------------
__global__ void k_zero_pool(float4* psum, float* pcnt, int G) {
    int t = blockIdx.x * blockDim.x + threadIdx.x;
    if (t < G * (DD/4)) psum[t] = make_float4(0.f, 0.f, 0.f, 0.f);
    if (t < G) pcnt[t] = 0.f;
}

__global__ __launch_bounds__(128)
void k_mlp(const float4* __restrict__ psum, const float* __restrict__ pcnt,
           const float* __restrict__ w1, const float* __restrict__ b1,
           const float* __restrict__ w2, const float* __restrict__ b2,
           float* __restrict__ out, int H) {
    __shared__ float p[DD];
    __shared__ float hid[128];
    int g   = blockIdx.x;
    int tid = threadIdx.x;

    float cnt = fmaxf(pcnt[g], 1.0f);
    float inv = 1.0f / cnt;
    const float* ps = (const float*)(psum + g * (DD/4));
    p[tid] = ps[tid] * inv;
    __syncthreads();

    if (tid < H) {
        float s = b1[tid];
#pragma unroll 8
        for (int k = 0; k < DD; k++) s += p[k] * w1[k * H + tid];
        hid[tid] = fmaxf(s, 0.f);
    }
    __syncthreads();

    if (tid < 4) {
        float s = b2[tid];
        for (int j = 0; j < H; j++) s += hid[j] * w2[j * 4 + tid];
        out[g * 4 + tid] = s;
    }
}

// ---------------------------------------------------------------------------
// Launch. NOTE: layer-0 GEMM is deliberately the 4th launch (ncu capture slot).
// ---------------------------------------------------------------------------
extern "C" void kernel_launch(void* const* d_in, const int* in_sizes, int n_in,
                              void* d_out, int out_size) {
    const float* x     = (const float*)d_in[0];
    const float* Ws    = (const float*)d_in[1];
    const float* bs    = (const float*)d_in[2];
    const float* w1    = (const float*)d_in[3];
    const float* b1    = (const float*)d_in[4];
    const float* w2    = (const float*)d_in[5];
    const float* b2    = (const float*)d_in[6];
    const int*   ei    = (const int*)d_in[7];
    const int*   batch = (const int*)d_in[8];
    float*       out   = (float*)d_out;

    const int N = in_sizes[8];          // 100000
    const int E = in_sizes[7] / 2;      // 1600000
    const int G = out_size / 4;         // 512
    const int H = in_sizes[4];          // 100

    int *cnt, *rowptr, *cur, *eadj, *bsum, *boff;
    float *dinv, *pcnt;
    uint32_t *Whi, *Wlo;
    __half2* y;
    float4 *hA, *hB, *psum;
    cudaGetSymbolAddress((void**)&cnt,    g_cnt);
    cudaGetSymbolAddress((void**)&rowptr, g_rowptr);
    cudaGetSymbolAddress((void**)&cur,    g_cur);
    cudaGetSymbolAddress((void**)&eadj,   g_eadj);
    cudaGetSymbolAddress((void**)&bsum,   g_bsum);
    cudaGetSymbolAddress((void**)&boff,   g_boff);
    cudaGetSymbolAddress((void**)&dinv,   g_dinv);
    cudaGetSymbolAddress((void**)&Whi,    g_Whi);
    cudaGetSymbolAddress((void**)&Wlo,    g_Wlo);
    cudaGetSymbolAddress((void**)&y,      g_y);
    cudaGetSymbolAddress((void**)&hA,     g_hA);
    cudaGetSymbolAddress((void**)&hB,     g_hB);
    cudaGetSymbolAddress((void**)&psum,   g_psum);
    cudaGetSymbolAddress((void**)&pcnt,   g_pcnt);

    const int T  = 256;
    const int nb = (N + SCAN_BLK - 1) / SCAN_BLK;
    const int gemmBlocks = (N + BM - 1) / BM;
    const int nodeWarpBlocks = (N + 7) / 8;

    // 1..3: prerequisites for GEMM0
    k_zero_cnt_splitW<<<(N + T - 1) / T, T>>>(cnt, N, Ws, Whi, Wlo);
    k_count          <<<(E + T - 1) / T, T>>>(ei, cnt, E);
    k_dinv           <<<(N + T - 1) / T, T>>>(cnt, dinv, N);

    // 4: layer-0 GEMM  (ncu capture slot)
    k_gemm_tf32<<<gemmBlocks, 256>>>((const float4*)x, (const uint4*)Whi,
                                     (const uint4*)Wlo, y, dinv, N, 0);

    // CSR build (independent of GEMM0 output)
    k_blocksum <<<nb, 256>>>(cnt, bsum, N);
    k_scanbsum <<<1, 128>>>(bsum, boff, rowptr, nb, N, E);
    k_scanblock<<<nb, SCAN_BLK>>>(cnt, boff, rowptr, cur, N);
    k_fill     <<<(E + T - 1) / T, T>>>(ei, cur, eadj, E);
    k_zero_pool<<<(G * (DD/4) + T - 1) / T, T>>>(psum, pcnt, G);

    // layer 0 scatter
    k_scatter_csr<<<nodeWarpBlocks, 256>>>((const uint2*)y, rowptr, eadj, dinv,
                                           bs + 0 * DD, hA,
                                           nullptr, nullptr, nullptr, N);

    // layers 1..3
    const float4* hin = (const float4*)hA;
    for (int L = 1; L < 4; L++) {
        k_gemm_tf32<<<gemmBlocks, 256>>>(hin, (const uint4*)(Whi + (size_t)L * DD * DD),
                                         (const uint4*)(Wlo + (size_t)L * DD * DD),
                                         y, dinv, N, 1);
        float4* hout = (L & 1) ? hB : hA;
        if (L < 3) {
            k_scatter_csr<<<nodeWarpBlocks, 256>>>((const uint2*)y, rowptr, eadj, dinv,
                                                   bs + L * DD, hout,
                                                   nullptr, nullptr, nullptr, N);
            hin = hout;
        } else {
            k_scatter_csr<<<nodeWarpBlocks, 256>>>((const uint2*)y, rowptr, eadj, dinv,
                                                   bs + L * DD, nullptr,
                                                   batch, psum, pcnt, N);
        }
    }

    k_mlp<<<G, 128>>>(psum, pcnt, w1, b1, w2, b2, out, H);
}

// round 9
// speedup vs baseline: 1.2554x; 1.2060x over previous
#include <cuda_runtime.h>
#include <cuda_fp16.h>
#include <cuda_bf16.h>
#include <cstdint>

// ---------------------------------------------------------------------------
// GCN_40037685134216: 4-layer GCN + mean-pool + MLP head, fp32.
// R9: GEMM -> bf16 m16n8k16 mma with 2-term split (3 mma terms), halving
//     mma instruction count and smem traffic vs 3xTF32. W pre-packed into
//     transposed bf16x2 hi/lo planes once per call.
// ---------------------------------------------------------------------------

#define MAX_N 100000
#define MAX_E 1600000
#define DD    128
#define MAX_G 512
#define SCAN_BLK 1024
#define NB ((MAX_N + SCAN_BLK - 1) / SCAN_BLK)   // 98
#define WPAIRS (4 * DD * (DD/2))                  // 32768 packed words per plane

__device__ __align__(16) int    g_cnt [MAX_N];
__device__ __align__(16) int    g_rowptr[MAX_N + 1];
__device__ __align__(16) int    g_cur [MAX_N];
__device__ __align__(16) int    g_eadj[MAX_E];
__device__ __align__(16) float  g_dinv[MAX_N];
__device__ __align__(16) int    g_bsum[NB];
__device__ __align__(16) int    g_boff[NB];
__device__ __align__(16) uint32_t g_Wbh[WPAIRS];  // bf16x2 hi, layout [L][n][kpair]
__device__ __align__(16) uint32_t g_Wbl[WPAIRS];  // bf16x2 lo
__device__ __align__(16) __half2 g_y [MAX_N * (DD/2)];   // fp16 messages
__device__ float4 g_hA [MAX_N * (DD/4)];
__device__ float4 g_hB [MAX_N * (DD/4)];
__device__ float4 g_psum[MAX_G * (DD/4)];
__device__ float  g_pcnt[MAX_G];

// ---------------------------------------------------------------------------
// zero cnt + pre-pack all 4 W matrices into transposed bf16x2 hi/lo planes.
// Wbh[L*8192 + n*64 + kp] = {bf16(W[2kp][n]), bf16(W[2kp+1][n])}
// ---------------------------------------------------------------------------
__device__ __forceinline__ void split_bf16_pair(float x0, float x1,
                                                uint32_t& hi, uint32_t& lo) {
    __nv_bfloat162 h2 = __floats2bfloat162_rn(x0, x1);
    float l0 = x0 - __low2float(h2);
    float l1 = x1 - __high2float(h2);
    __nv_bfloat162 l2 = __floats2bfloat162_rn(l0, l1);
    hi = *reinterpret_cast<uint32_t*>(&h2);
    lo = *reinterpret_cast<uint32_t*>(&l2);
}

__global__ void k_zero_cnt_packW(int* cnt, int N, const float* __restrict__ Ws,
                                 uint32_t* __restrict__ Wbh, uint32_t* __restrict__ Wbl) {
    int i = blockIdx.x * blockDim.x + threadIdx.x;
    if (i < N) cnt[i] = 0;
    if (i < WPAIRS) {
        int L   = i >> 13;            // / 8192
        int rem = i & 8191;
        int n   = rem >> 6;           // / 64
        int kp  = rem & 63;
        const float* W = Ws + (size_t)L * DD * DD;
        float a = W[(2 * kp) * DD + n];
        float b = W[(2 * kp + 1) * DD + n];
        uint32_t h, l;
        split_bf16_pair(a, b, h, l);
        Wbh[i] = h;
        Wbl[i] = l;
    }
}

__global__ void k_count(const int* __restrict__ ei, int* cnt, int E) {
    int e = blockIdx.x * blockDim.x + threadIdx.x;
    if (e < E) atomicAdd(&cnt[ei[E + e]], 1);
}

__global__ void k_dinv(const int* __restrict__ cnt, float* dinv, int N) {
    int i = blockIdx.x * blockDim.x + threadIdx.x;
    if (i < N) dinv[i] = rsqrtf((float)cnt[i] + 1.0f);  // +1 self loop
}

__global__ __launch_bounds__(256)
void k_blocksum(const int* __restrict__ cnt, int* __restrict__ bsum, int N) {
    __shared__ int red[8];
    int b = blockIdx.x, t = threadIdx.x;
    int base = b * SCAN_BLK;
    int s = 0;
#pragma unroll
    for (int j = 0; j < 4; j++) {
        int i = base + t + j * 256;
        if (i < N) s += cnt[i];
    }
#pragma unroll
    for (int off = 16; off > 0; off >>= 1)
        s += __shfl_down_sync(0xffffffffu, s, off);
    if ((t & 31) == 0) red[t >> 5] = s;
    __syncthreads();
    if (t < 8) {
        s = red[t];
#pragma unroll
        for (int off = 4; off > 0; off >>= 1)
            s += __shfl_down_sync(0xffu, s, off);
        if (t == 0) bsum[b] = s;
    }
}

__global__ __launch_bounds__(128)
void k_scanbsum(const int* __restrict__ bsum, int* __restrict__ boff,
                int* __restrict__ rowptr, int nb, int N, int E) {
    __shared__ int s[128];
    int t = threadIdx.x;
    int v = (t < nb) ? bsum[t] : 0;
    s[t] = v;
    __syncthreads();
    for (int off = 1; off < 128; off <<= 1) {
        int u = (t >= off) ? s[t - off] : 0;
        __syncthreads();
        s[t] += u;
        __syncthreads();
    }
    if (t < nb) boff[t] = s[t] - v;
    if (t == 0) rowptr[N] = E;
}

__global__ __launch_bounds__(SCAN_BLK)
void k_scanblock(const int* __restrict__ cnt, const int* __restrict__ boff,
                 int* __restrict__ rowptr, int* __restrict__ cur, int N) {
    __shared__ int s[SCAN_BLK];
    int b = blockIdx.x, t = threadIdx.x;
    int i = b * SCAN_BLK + t;
    int v = (i < N) ? cnt[i] : 0;
    s[t] = v;
    __syncthreads();
    for (int off = 1; off < SCAN_BLK; off <<= 1) {
        int u = (t >= off) ? s[t - off] : 0;
        __syncthreads();
        s[t] += u;
        __syncthreads();
    }
    if (i < N) {
        int ex = boff[b] + s[t] - v;
        rowptr[i] = ex;
        cur[i]    = ex;
    }
}

__global__ void k_fill(const int* __restrict__ ei, int* cur,
                       int* __restrict__ eadj, int E) {
    int e = blockIdx.x * blockDim.x + threadIdx.x;
    if (e < E) {
        int r = ei[e];
        int c = ei[E + e];
        int pos = atomicAdd(&cur[c], 1);
        eadj[pos] = r;
    }
}

// ---------------------------------------------------------------------------
// bf16 tensor-core GEMM: Y[M,128] = fp16( dinv[m] * ( act(A[M,128]) @ W ) )
// 2-term bf16 split: a=ah+al, b=bh+bl; acc += ah*bh + ah*bl + al*bh.
// mma.m16n8k16. 256 threads = 8 warps (4 M-bands x 2 N-bands).
// ---------------------------------------------------------------------------
#define BM  128
#define PA2 12    // A smem pitch in words (bf16x2) - conflict-free
#define PWT 12    // W smem pitch in words - conflict-free

__device__ __forceinline__ void mma_bf16(float* c, const uint32_t* a, const uint32_t* b) {
    asm volatile("mma.sync.aligned.m16n8k16.row.col.f32.bf16.bf16.f32 "
                 "{%0,%1,%2,%3}, {%4,%5,%6,%7}, {%8,%9}, {%0,%1,%2,%3};"
                 : "+f"(c[0]), "+f"(c[1]), "+f"(c[2]), "+f"(c[3])
                 : "r"(a[0]), "r"(a[1]), "r"(a[2]), "r"(a[3]),
                   "r"(b[0]), "r"(b[1]));
}

__global__ __launch_bounds__(256)
void k_gemm_bf16(const float4* __restrict__ A4,
                 const uint4* __restrict__ Wbh4, const uint4* __restrict__ Wbl4,
                 __half2* __restrict__ Y2, const float* __restrict__ dinv,
                 int M, int applyRelu) {
    __shared__ uint32_t Ah[BM * PA2], Al[BM * PA2];
    __shared__ uint32_t Wh[DD * PWT], Wl[DD * PWT];

    const int tid  = threadIdx.x;
    const int lane = tid & 31;
    const int wid  = tid >> 5;
    const int wm   = wid & 3;        // M band (32 rows)
    const int wn   = wid >> 2;       // N band (64 cols)
    const int grp  = lane >> 2;
    const int tig  = lane & 3;
    const int m0   = blockIdx.x * BM;

    float acc[2][8][4];
#pragma unroll
    for (int f = 0; f < 2; f++)
#pragma unroll
        for (int g = 0; g < 8; g++)
#pragma unroll
            for (int j = 0; j < 4; j++) acc[f][g][j] = 0.0f;

    for (int c = 0; c < 8; c++) {            // k-chunk of 16 (8 kpairs)
        // --- A tile: 128 rows x 16 k (4 float4 per row), relu, bf16 split ---
#pragma unroll
        for (int i = 0; i < 2; i++) {
            int id  = tid + i * 256;          // 0..511
            int row = id >> 2;                // 0..127
            int q   = id & 3;                 // float4 within chunk
            float4 v = make_float4(0.f, 0.f, 0.f, 0.f);
            int gr = m0 + row;
            if (gr < M) v = A4[gr * (DD/4) + c * 4 + q];
            if (applyRelu) {
                v.x = fmaxf(v.x, 0.f); v.y = fmaxf(v.y, 0.f);
                v.z = fmaxf(v.z, 0.f); v.w = fmaxf(v.w, 0.f);
            }
            uint32_t h0, l0, h1, l1;
            split_bf16_pair(v.x, v.y, h0, l0);
            split_bf16_pair(v.z, v.w, h1, l1);
            int base = row * PA2 + q * 2;
            Ah[base]     = h0; Ah[base + 1] = h1;
            Al[base]     = l0; Al[base + 1] = l1;
        }
        // --- W tile: 128 n x 8 kpair words, pre-packed, uint4 copy ---
        {
            int n    = tid >> 1;              // 0..127
            int half = tid & 1;               // 0..1
            uint4 vh = Wbh4[n * 16 + c * 2 + half];
            uint4 vl = Wbl4[n * 16 + c * 2 + half];
            int base = n * PWT + half * 4;
            Wh[base + 0] = vh.x; Wh[base + 1] = vh.y;
            Wh[base + 2] = vh.z; Wh[base + 3] = vh.w;
            Wl[base + 0] = vl.x; Wl[base + 1] = vl.y;
            Wl[base + 2] = vl.z; Wl[base + 3] = vl.w;
        }
        __syncthreads();

        // fragments (one m16n8k16 step covers the whole 16-k chunk)
        uint32_t ah[2][4], al[2][4];
#pragma unroll
        for (int f = 0; f < 2; f++) {
            int r0 = wm * 32 + f * 16 + grp;
            ah[f][0] = Ah[r0 * PA2 + tig];
            ah[f][1] = Ah[(r0 + 8) * PA2 + tig];
            ah[f][2] = Ah[r0 * PA2 + tig + 4];
            ah[f][3] = Ah[(r0 + 8) * PA2 + tig + 4];
            al[f][0] = Al[r0 * PA2 + tig];
            al[f][1] = Al[(r0 + 8) * PA2 + tig];
            al[f][2] = Al[r0 * PA2 + tig + 4];
            al[f][3] = Al[(r0 + 8) * PA2 + tig + 4];
        }
        uint32_t bh[8][2], bl[8][2];
#pragma unroll
        for (int g = 0; g < 8; g++) {
            int n = wn * 64 + g * 8 + grp;
            bh[g][0] = Wh[n * PWT + tig];
            bh[g][1] = Wh[n * PWT + tig + 4];
            bl[g][0] = Wl[n * PWT + tig];
            bl[g][1] = Wl[n * PWT + tig + 4];
        }
#pragma unroll
        for (int f = 0; f < 2; f++)
#pragma unroll
            for (int g = 0; g < 8; g++) {
                mma_bf16(acc[f][g], ah[f], bl[g]);
                mma_bf16(acc[f][g], al[f], bh[g]);
                mma_bf16(acc[f][g], ah[f], bh[g]);
            }
        __syncthreads();
    }

    // Epilogue: scale by dinv[row], convert to half2, store.
#pragma unroll
    for (int f = 0; f < 2; f++) {
        int r0 = m0 + wm * 32 + f * 16 + grp;
        int r1 = r0 + 8;
        float d0 = (r0 < M) ? dinv[r0] : 0.f;
        float d1 = (r1 < M) ? dinv[r1] : 0.f;
#pragma unroll
        for (int g = 0; g < 8; g++) {
            int cc = wn * 64 + g * 8 + tig * 2;
            if (r0 < M)
                Y2[(size_t)r0 * (DD/2) + (cc >> 1)] =
                    __floats2half2_rn(acc[f][g][0] * d0, acc[f][g][1] * d0);
            if (r1 < M)
                Y2[(size_t)r1 * (DD/2) + (cc >> 1)] =
                    __floats2half2_rn(acc[f][g][2] * d1, acc[f][g][3] * d1);
        }
    }
}

// ---------------------------------------------------------------------------
// CSR scatter (R6 form): one warp per node.
// ---------------------------------------------------------------------------
__device__ __forceinline__ void red_add_v4(float* addr, float4 v) {
    asm volatile("red.global.add.v4.f32 [%0], {%1, %2, %3, %4};"
                 :: "l"(addr), "f"(v.x), "f"(v.y), "f"(v.z), "f"(v.w)
                 : "memory");
}

__device__ __forceinline__ void acc_half4(float4& acc, uint2 raw) {
    __half2 h01 = *reinterpret_cast<__half2*>(&raw.x);
    __half2 h23 = *reinterpret_cast<__half2*>(&raw.y);
    float2 f01 = __half22float2(h01);
    float2 f23 = __half22float2(h23);
    acc.x += f01.x; acc.y += f01.y; acc.z += f23.x; acc.w += f23.y;
}

__global__ __launch_bounds__(256)
void k_scatter_csr(const uint2* __restrict__ y2,   // [N][32] uint2 (=4 halves)
                   const int* __restrict__ rowptr,
                   const int* __restrict__ eadj,
                   const float* __restrict__ dinv,
                   const float* __restrict__ bias,
                   float4* __restrict__ out4,
                   const int* __restrict__ batch,   // non-null => pool mode
                   float4* __restrict__ psum, float* __restrict__ pcnt,
                   int N) {
    int node = (blockIdx.x * blockDim.x + threadIdx.x) >> 5;
    int lane = threadIdx.x & 31;
    if (node >= N) return;

    int beg = rowptr[node];
    int end = rowptr[node + 1];

    float4 acc = make_float4(0.f, 0.f, 0.f, 0.f);
    acc_half4(acc, y2[(size_t)node * 32 + lane]);   // self loop
    for (int base = beg; base < end; base += 32) {
        int n = min(32, end - base);
        int s = (base + lane < end) ? eadj[base + lane] : 0;
#pragma unroll 4
        for (int j = 0; j < n; j++) {
            int src = __shfl_sync(0xffffffffu, s, j);
            acc_half4(acc, y2[(size_t)src * 32 + lane]);
        }
    }
    float di = dinv[node];
    const float4 b = ((const float4*)bias)[lane];
    float4 o;
    o.x = fmaf(acc.x, di, b.x);
    o.y = fmaf(acc.y, di, b.y);
    o.z = fmaf(acc.z, di, b.z);
    o.w = fmaf(acc.w, di, b.w);

    if (batch) {
        int g = batch[node];
        red_add_v4((float*)(psum + g * (DD/4) + lane), o);
        if (lane == 0) atomicAdd(&pcnt[g], 1.0f);
    } else {
        out4[(size_t)node * (DD/4) + lane] = o;
    }
}

// ---------------------------------------------------------------------------
// Pool zero + MLP head
// ---------------------------------------------------------------------------
__global__ void k_zero_pool(float4* psum, float* pcnt, int G) {
    int t = blockIdx.x * blockDim.x + threadIdx.x;
    if (t < G * (DD/4)) psum[t] = make_float4(0.f, 0.f, 0.f, 0.f);
    if (t < G) pcnt[t] = 0.f;
}

__global__ __launch_bounds__(128)
void k_mlp(const float4* __restrict__ psum, const float* __restrict__ pcnt,
           const float* __restrict__ w1, const float* __restrict__ b1,
           const float* __restrict__ w2, const float* __restrict__ b2,
           float* __restrict__ out, int H) {
    __shared__ float p[DD];
    __shared__ float hid[128];
    int g   = blockIdx.x;
    int tid = threadIdx.x;

    float cnt = fmaxf(pcnt[g], 1.0f);
    float inv = 1.0f / cnt;
    const float* ps = (const float*)(psum + g * (DD/4));
    p[tid] = ps[tid] * inv;
    __syncthreads();

    if (tid < H) {
        float s = b1[tid];
#pragma unroll 8
        for (int k = 0; k < DD; k++) s += p[k] * w1[k * H + tid];
        hid[tid] = fmaxf(s, 0.f);
    }
    __syncthreads();

    if (tid < 4) {
        float s = b2[tid];
        for (int j = 0; j < H; j++) s += hid[j] * w2[j * 4 + tid];
        out[g * 4 + tid] = s;
    }
}

// ---------------------------------------------------------------------------
// Launch. Layer-0 GEMM kept as the 4th launch (ncu capture slot).
// ---------------------------------------------------------------------------
extern "C" void kernel_launch(void* const* d_in, const int* in_sizes, int n_in,
                              void* d_out, int out_size) {
    const float* x     = (const float*)d_in[0];
    const float* Ws    = (const float*)d_in[1];
    const float* bs    = (const float*)d_in[2];
    const float* w1    = (const float*)d_in[3];
    const float* b1    = (const float*)d_in[4];
    const float* w2    = (const float*)d_in[5];
    const float* b2    = (const float*)d_in[6];
    const int*   ei    = (const int*)d_in[7];
    const int*   batch = (const int*)d_in[8];
    float*       out   = (float*)d_out;

    const int N = in_sizes[8];          // 100000
    const int E = in_sizes[7] / 2;      // 1600000
    const int G = out_size / 4;         // 512
    const int H = in_sizes[4];          // 100

    int *cnt, *rowptr, *cur, *eadj, *bsum, *boff;
    float *dinv, *pcnt;
    uint32_t *Wbh, *Wbl;
    __half2* y;
    float4 *hA, *hB, *psum;
    cudaGetSymbolAddress((void**)&cnt,    g_cnt);
    cudaGetSymbolAddress((void**)&rowptr, g_rowptr);
    cudaGetSymbolAddress((void**)&cur,    g_cur);
    cudaGetSymbolAddress((void**)&eadj,   g_eadj);
    cudaGetSymbolAddress((void**)&bsum,   g_bsum);
    cudaGetSymbolAddress((void**)&boff,   g_boff);
    cudaGetSymbolAddress((void**)&dinv,   g_dinv);
    cudaGetSymbolAddress((void**)&Wbh,    g_Wbh);
    cudaGetSymbolAddress((void**)&Wbl,    g_Wbl);
    cudaGetSymbolAddress((void**)&y,      g_y);
    cudaGetSymbolAddress((void**)&hA,     g_hA);
    cudaGetSymbolAddress((void**)&hB,     g_hB);
    cudaGetSymbolAddress((void**)&psum,   g_psum);
    cudaGetSymbolAddress((void**)&pcnt,   g_pcnt);

    const int T  = 256;
    const int nb = (N + SCAN_BLK - 1) / SCAN_BLK;
    const int gemmBlocks = (N + BM - 1) / BM;
    const int nodeWarpBlocks = (N + 7) / 8;

    // 1..3: prerequisites for GEMM0
    k_zero_cnt_packW<<<(N + T - 1) / T, T>>>(cnt, N, Ws, Wbh, Wbl);
    k_count         <<<(E + T - 1) / T, T>>>(ei, cnt, E);
    k_dinv          <<<(N + T - 1) / T, T>>>(cnt, dinv, N);

    // 4: layer-0 GEMM  (ncu capture slot)
    k_gemm_bf16<<<gemmBlocks, 256>>>((const float4*)x, (const uint4*)Wbh,
                                     (const uint4*)Wbl, y, dinv, N, 0);

    // CSR build (independent of GEMM0 output)
    k_blocksum <<<nb, 256>>>(cnt, bsum, N);
    k_scanbsum <<<1, 128>>>(bsum, boff, rowptr, nb, N, E);
    k_scanblock<<<nb, SCAN_BLK>>>(cnt, boff, rowptr, cur, N);
    k_fill     <<<(E + T - 1) / T, T>>>(ei, cur, eadj, E);
    k_zero_pool<<<(G * (DD/4) + T - 1) / T, T>>>(psum, pcnt, G);

    // layer 0 scatter
    k_scatter_csr<<<nodeWarpBlocks, 256>>>((const uint2*)y, rowptr, eadj, dinv,
                                           bs + 0 * DD, hA,
                                           nullptr, nullptr, nullptr, N);

    // layers 1..3
    const float4* hin = (const float4*)hA;
    for (int L = 1; L < 4; L++) {
        k_gemm_bf16<<<gemmBlocks, 256>>>(hin,
                                         (const uint4*)(Wbh + (size_t)L * 8192),
                                         (const uint4*)(Wbl + (size_t)L * 8192),
                                         y, dinv, N, 1);
        float4* hout = (L & 1) ? hB : hA;
        if (L < 3) {
            k_scatter_csr<<<nodeWarpBlocks, 256>>>((const uint2*)y, rowptr, eadj, dinv,
                                                   bs + L * DD, hout,
                                                   nullptr, nullptr, nullptr, N);
            hin = hout;
        } else {
            k_scatter_csr<<<nodeWarpBlocks, 256>>>((const uint2*)y, rowptr, eadj, dinv,
                                                   bs + L * DD, nullptr,
                                                   batch, psum, pcnt, N);
        }
    }

    k_mlp<<<G, 128>>>(psum, pcnt, w1, b1, w2, b2, out, H);
}